// round 15
// baseline (speedup 1.0000x reference)
#include <cuda_runtime.h>
#include <cuda_bf16.h>
#include <cuda_fp16.h>
#include <stdint.h>
#include <math.h>

// Problem constants: B=1, E=128, L=256, D=768, H=12, DH=64
#define EE 128
#define LL 256
#define DD 768
#define D3 2304
#define NROWS 32768          // E*L
#define NEGV (-10000.0f)

typedef unsigned long long ull;

// ------------------------- scratch (static device globals; no runtime alloc) -------------------------
__device__ __half g_qkvh[(size_t)NROWS * D3];  // 151 MB (fp16 qkv from GEMM)
__device__ float  g_tmp[(size_t)NROWS * DD];   // 100 MB
__device__ __half g_acvh[(size_t)NROWS * DD];  // 50 MB (fp16 activations)
__device__ __half g_wcvh[(size_t)D3 * DD];     // 3.5 MB (fp16 weights)
__device__ float  g_neg[NROWS];

// ------------------------- PTX helpers -------------------------
__device__ __forceinline__ uint32_t smem_u32(const void* p) {
    uint32_t a;
    asm("{ .reg .u64 t; cvta.to.shared.u64 t, %1; cvt.u32.u64 %0, t; }" : "=r"(a) : "l"(p));
    return a;
}
__device__ __forceinline__ void cp_async16(uint32_t dst, const void* src) {
    asm volatile("cp.async.cg.shared.global [%0], [%1], 16;" :: "r"(dst), "l"(src) : "memory");
}
// fp16 m16n8k16, fp32 accum
__device__ __forceinline__ void mma16(float* c, uint32_t a0, uint32_t a1, uint32_t a2, uint32_t a3,
                                      uint32_t b0, uint32_t b1) {
    asm volatile(
        "mma.sync.aligned.m16n8k16.row.col.f32.f16.f16.f32 "
        "{%0,%1,%2,%3}, {%4,%5,%6,%7}, {%8,%9}, {%0,%1,%2,%3};"
        : "+f"(c[0]), "+f"(c[1]), "+f"(c[2]), "+f"(c[3])
        : "r"(a0), "r"(a1), "r"(a2), "r"(a3), "r"(b0), "r"(b1));
}
__device__ __forceinline__ void ldsm_x4(uint32_t& r0, uint32_t& r1, uint32_t& r2, uint32_t& r3,
                                        uint32_t addr) {
    asm volatile("ldmatrix.sync.aligned.m8n8.x4.shared.b16 {%0,%1,%2,%3}, [%4];"
                 : "=r"(r0), "=r"(r1), "=r"(r2), "=r"(r3) : "r"(addr));
}
__device__ __forceinline__ void ldsm_x4_t(uint32_t& r0, uint32_t& r1, uint32_t& r2, uint32_t& r3,
                                          uint32_t addr) {
    asm volatile("ldmatrix.sync.aligned.m8n8.x4.trans.shared.b16 {%0,%1,%2,%3}, [%4];"
                 : "=r"(r0), "=r"(r1), "=r"(r2), "=r"(r3) : "r"(addr));
}

// ------------------------- padding mask -> additive neg, with dtype auto-detect -------------------------
__global__ void neg_kernel(const void* mraw) {
    __shared__ int notInt, notFloat;
    int tid = threadIdx.x;
    if (tid == 0) { notInt = 0; notFloat = 0; }
    __syncthreads();
    const unsigned int* w = (const unsigned int*)mraw;
    int badI = 0, badF = 0;
    for (int i = tid; i < 8192; i += 256) {
        unsigned int v = w[i];
        if (v > 1u) badI = 1;
        if (v != 0u && v != 0x3F800000u) badF = 1;
    }
    if (badI) notInt = 1;
    if (badF) notFloat = 1;
    __syncthreads();
    int mode = (!notInt) ? 0 : ((!notFloat) ? 1 : 2);  // 0=int32, 1=float32, 2=uint8
    for (int i = tid; i < NROWS; i += 256) {
        bool m;
        if (mode == 0)      m = ((const int*)mraw)[i] != 0;
        else if (mode == 1) m = ((const float*)mraw)[i] != 0.0f;
        else                m = ((const unsigned char*)mraw)[i] != 0;
        g_neg[i] = m ? NEGV : 0.0f;
    }
}

// ------------------------- fp32 -> fp16 pre-pass (8 elements/thread) -------------------------
__global__ __launch_bounds__(256)
void cvt_h_kernel(const float* __restrict__ in, __half* __restrict__ out) {
    size_t i = ((size_t)blockIdx.x * 256 + threadIdx.x) * 8;
    float4 v0 = *(const float4*)(in + i);
    float4 v1 = *(const float4*)(in + i + 4);
    __half2 h0 = __floats2half2_rn(v0.x, v0.y);
    __half2 h1 = __floats2half2_rn(v0.z, v0.w);
    __half2 h2 = __floats2half2_rn(v1.x, v1.y);
    __half2 h3 = __floats2half2_rn(v1.z, v1.w);
    uint4 u;
    u.x = *(uint32_t*)&h0; u.y = *(uint32_t*)&h1;
    u.z = *(uint32_t*)&h2; u.w = *(uint32_t*)&h3;
    *(uint4*)(out + i) = u;
}

// ------------------------- fp16 mma GEMM (unchanged from R14) -------------------------
#define GM 128
#define GN 128
#define KB 32
#define NST 24                       // 768/32
#define KS2 20                       // row stride in half2 units (80 B/row)
#define AU (GM * KS2)
#define BU (GN * KS2)
#define STAGEU (AU + BU)             // 5120 uint32 = 20480 B
#define GEMM_SMEM (3 * STAGEU * 4)   // 61440 bytes

__device__ __forceinline__ void load_stage(uint32_t* smu, int stg, const __half* Ah, const __half* Wh,
                                           int k0, int tid) {
    uint32_t as_u = smem_u32(smu + stg * STAGEU);
    uint32_t bs_u = as_u + AU * 4;
#pragma unroll
    for (int i = 0; i < 2; i++) {
        int idx = tid + i * 256;
        int row = idx >> 2, ch = idx & 3;
        cp_async16(as_u + row * (KS2 * 4) + ch * 16, Ah + (size_t)row * DD + k0 + ch * 8);
    }
#pragma unroll
    for (int i = 0; i < 2; i++) {
        int idx = tid + i * 256;
        int row = idx >> 2, ch = idx & 3;
        cp_async16(bs_u + row * (KS2 * 4) + ch * 16, Wh + (size_t)row * DD + k0 + ch * 8);
    }
}

__global__ __launch_bounds__(256, 2)
void gemm_mma_kernel(const __half* __restrict__ A, const __half* __restrict__ W,
                     const float* __restrict__ bias, __half* __restrict__ C) {
    extern __shared__ uint32_t smu[];
    int tid = threadIdx.x, lane = tid & 31, w = tid >> 5;
    int wm = w & 3, wn = w >> 2;
    int m0 = blockIdx.y * GM, n0 = blockIdx.x * GN;
    const __half* Ah = A + (size_t)m0 * DD;
    const __half* Wh = W + (size_t)n0 * DD;
    int r0 = lane >> 2, c0 = lane & 3;

    uint32_t a_off = (uint32_t)((wm * 32 + (lane & 15)) * 80 + (lane >> 4) * 16);
    uint32_t b_off = (uint32_t)((wn * 64 + ((lane >> 4) & 1) * 8 + (lane & 7)) * 80
                                + ((lane >> 3) & 1) * 16);

    float acc[2][8][4];
#pragma unroll
    for (int mt = 0; mt < 2; mt++)
#pragma unroll
        for (int nt = 0; nt < 8; nt++)
#pragma unroll
            for (int q = 0; q < 4; q++) acc[mt][nt][q] = 0.0f;

    load_stage(smu, 0, Ah, Wh, 0, tid);
    asm volatile("cp.async.commit_group;" ::: "memory");
    load_stage(smu, 1, Ah, Wh, KB, tid);
    asm volatile("cp.async.commit_group;" ::: "memory");

    uint32_t sbase = smem_u32(smu);

    for (int s = 0; s < NST; ++s) {
        int b = s % 3;
        asm volatile("cp.async.wait_group 1;" ::: "memory");
        __syncthreads();
        if (s + 2 < NST) load_stage(smu, (s + 2) % 3, Ah, Wh, (s + 2) * KB, tid);
        asm volatile("cp.async.commit_group;" ::: "memory");

        uint32_t as_u = sbase + b * (STAGEU * 4);
        uint32_t bs_u = as_u + AU * 4;
#pragma unroll
        for (int ks = 0; ks < 2; ks++) {
            uint32_t koff = ks * 32;
            uint32_t bf[8][2];
#pragma unroll
            for (int ntp = 0; ntp < 4; ntp++) {
                uint32_t r0v, r1v, r2v, r3v;
                ldsm_x4(r0v, r1v, r2v, r3v, bs_u + b_off + ntp * (16 * 80) + koff);
                bf[ntp * 2][0] = r0v;     bf[ntp * 2][1] = r1v;
                bf[ntp * 2 + 1][0] = r2v; bf[ntp * 2 + 1][1] = r3v;
            }
#pragma unroll
            for (int mt = 0; mt < 2; mt++) {
                uint32_t a0, a1, a2, a3;
                ldsm_x4(a0, a1, a2, a3, as_u + a_off + mt * (16 * 80) + koff);
#pragma unroll
                for (int nt = 0; nt < 8; nt++)
                    mma16(acc[mt][nt], a0, a1, a2, a3, bf[nt][0], bf[nt][1]);
            }
        }
    }
    asm volatile("cp.async.wait_group 0;" ::: "memory");

#pragma unroll
    for (int nt = 0; nt < 8; nt++) {
        int col = n0 + wn * 64 + nt * 8 + c0 * 2;
        float b0v = bias[col], b1v = bias[col + 1];
#pragma unroll
        for (int mt = 0; mt < 2; mt++) {
            int row = m0 + wm * 32 + mt * 16 + r0;
            __half2 h0 = __floats2half2_rn(acc[mt][nt][0] + b0v, acc[mt][nt][1] + b1v);
            __half2 h1 = __floats2half2_rn(acc[mt][nt][2] + b0v, acc[mt][nt][3] + b1v);
            *(uint32_t*)&C[(size_t)row * D3 + col] = *(uint32_t*)&h0;
            *(uint32_t*)&C[(size_t)(row + 8) * D3 + col] = *(uint32_t*)&h1;
        }
    }
}

// ------------------------- fp16 tensor-core attention (ldmatrix everywhere) -------------------------
#define HSTR 36      // half2 stride for Q/K/V rows (144 B)

template<int S>
__global__ __launch_bounds__(256, 2)
void attn_tc_kernel(const __half* __restrict__ qkv,
                    long groupStride, long posStride,
                    const float* __restrict__ neg, long negGroupStride, long negStride,
                    float* __restrict__ outp, long outGroupStride, long outPosStride) {
    constexpr int PS2 = S / 2 + 4;      // 132 / 68 half2 (row = 33/17 x 16B, banks 4r)
    constexpr int CW = S / 8;
    constexpr int NTQ = CW / 8;         // 4 (S=256) / 2 (S=128)
    constexpr int VOFF = 0;
    constexpr int KOFF = VOFF + S * 144;
    constexpr int QOFF = KOFF + S * 144;
    constexpr int NOFF = QOFF + 64 * 144;
    constexpr int MOFF = NOFF + S * 4;
    extern __shared__ char smc[];
    float* negs = (float*)(smc + NOFF);
    float* pmax = (float*)(smc + MOFF);
    float* psum = (float*)(smc + MOFF + 2048);

    int h   = blockIdx.y;
    int grp = blockIdx.z;
    int i0  = blockIdx.x * 64;
    const __half* base = qkv + (size_t)grp * groupStride;
    const __half* qb = base + h * 64;
    const __half* kb = base + 768 + h * 64;
    const __half* vb = base + 1536 + h * 64;
    int tid = threadIdx.x;

    for (int idx = tid; idx < S * 8; idx += 256) {
        int j = idx >> 3, c8 = idx & 7;
        uint4 kv4 = *(const uint4*)(kb + (size_t)j * posStride + c8 * 8);
        uint4 vv4 = *(const uint4*)(vb + (size_t)j * posStride + c8 * 8);
        *(uint4*)(smc + KOFF + j * 144 + c8 * 16) = kv4;
        *(uint4*)(smc + VOFF + j * 144 + c8 * 16) = vv4;
    }
    {
        __half2 sc = __floats2half2_rn(0.125f, 0.125f);
        for (int idx = tid; idx < 64 * 8; idx += 256) {
            int i = idx >> 3, c8 = idx & 7;
            uint4 q4 = *(const uint4*)(qb + (size_t)(i0 + i) * posStride + c8 * 8);
            __half2* qh = (__half2*)&q4;
            qh[0] = __hmul2(qh[0], sc); qh[1] = __hmul2(qh[1], sc);
            qh[2] = __hmul2(qh[2], sc); qh[3] = __hmul2(qh[3], sc);
            *(uint4*)(smc + QOFF + i * 144 + c8 * 16) = q4;
        }
    }
    if (tid < S) negs[tid] = neg[(size_t)grp * negGroupStride + (size_t)tid * negStride];
    __syncthreads();

    int w = tid >> 5, lane = tid & 31;
    int r0 = lane >> 2, c0 = lane & 3;
    int colb = w * CW;

    // ldmatrix per-lane addresses
    uint32_t qa_addr = smem_u32(smc + QOFF) + (lane & 15) * 144 + (lane >> 4) * 16;
    uint32_t kb_addr = smem_u32(smc + KOFF)
                     + (colb + ((lane >> 4) & 1) * 8 + (lane & 7)) * 144
                     + ((lane >> 3) & 1) * 16;

    // ---- QK^T (fp16 m16n8k16): all 64 rows x CW-col strip per warp ----
    float acc[4][NTQ][4];
#pragma unroll
    for (int mt = 0; mt < 4; mt++)
#pragma unroll
        for (int nt = 0; nt < NTQ; nt++)
#pragma unroll
            for (int q = 0; q < 4; q++) acc[mt][nt][q] = 0.0f;

#pragma unroll
    for (int kc = 0; kc < 4; kc++) {
        uint32_t koff = kc * 32;
        uint32_t bfr[NTQ][2];
#pragma unroll
        for (int ntp = 0; ntp < NTQ / 2; ntp++) {
            uint32_t r0v, r1v, r2v, r3v;
            ldsm_x4(r0v, r1v, r2v, r3v, kb_addr + ntp * (16 * 144) + koff);
            bfr[ntp * 2][0] = r0v;     bfr[ntp * 2][1] = r1v;
            bfr[ntp * 2 + 1][0] = r2v; bfr[ntp * 2 + 1][1] = r3v;
        }
#pragma unroll
        for (int mt = 0; mt < 4; mt++) {
            uint32_t a0, a1, a2, a3;
            ldsm_x4(a0, a1, a2, a3, qa_addr + mt * (16 * 144) + koff);
#pragma unroll
            for (int nt = 0; nt < NTQ; nt++)
                mma16(acc[mt][nt], a0, a1, a2, a3, bfr[nt][0], bfr[nt][1]);
        }
    }

    // ---- mask + per-warp partial row max ----
    float mlo[4], mhi[4];
#pragma unroll
    for (int mt = 0; mt < 4; mt++) { mlo[mt] = -3.4e38f; mhi[mt] = -3.4e38f; }
#pragma unroll
    for (int nt = 0; nt < NTQ; nt++) {
        int cA = colb + nt * 8 + c0 * 2;
        float n0v = negs[cA], n1v = negs[cA + 1];
#pragma unroll
        for (int mt = 0; mt < 4; mt++) {
            acc[mt][nt][0] += n0v; acc[mt][nt][1] += n1v;
            acc[mt][nt][2] += n0v; acc[mt][nt][3] += n1v;
            mlo[mt] = fmaxf(mlo[mt], fmaxf(acc[mt][nt][0], acc[mt][nt][1]));
            mhi[mt] = fmaxf(mhi[mt], fmaxf(acc[mt][nt][2], acc[mt][nt][3]));
        }
    }
#pragma unroll
    for (int mt = 0; mt < 4; mt++) {
#pragma unroll
        for (int o = 1; o <= 2; o <<= 1) {
            mlo[mt] = fmaxf(mlo[mt], __shfl_xor_sync(0xffffffffu, mlo[mt], o));
            mhi[mt] = fmaxf(mhi[mt], __shfl_xor_sync(0xffffffffu, mhi[mt], o));
        }
        if (c0 == 0) {
            pmax[w * 64 + mt * 16 + r0] = mlo[mt];
            pmax[w * 64 + mt * 16 + r0 + 8] = mhi[mt];
        }
    }
    __syncthreads();   // pmax ready; all warps done reading K

    // ---- global max, exp, partial sums, write P (fp16, aliases K) ----
    uint32_t* Pu = (uint32_t*)(smc + KOFF);
#pragma unroll
    for (int mt = 0; mt < 4; mt++) {
        int R = mt * 16 + r0;
        float gmlo = pmax[R], gmhi = pmax[R + 8];
#pragma unroll
        for (int ww = 1; ww < 8; ww++) {
            gmlo = fmaxf(gmlo, pmax[ww * 64 + R]);
            gmhi = fmaxf(gmhi, pmax[ww * 64 + R + 8]);
        }
        float slo = 0.0f, shi = 0.0f;
#pragma unroll
        for (int nt = 0; nt < NTQ; nt++) {
            acc[mt][nt][0] = __expf(acc[mt][nt][0] - gmlo);
            acc[mt][nt][1] = __expf(acc[mt][nt][1] - gmlo);
            acc[mt][nt][2] = __expf(acc[mt][nt][2] - gmhi);
            acc[mt][nt][3] = __expf(acc[mt][nt][3] - gmhi);
            slo += acc[mt][nt][0] + acc[mt][nt][1];
            shi += acc[mt][nt][2] + acc[mt][nt][3];
        }
#pragma unroll
        for (int o = 1; o <= 2; o <<= 1) {
            slo += __shfl_xor_sync(0xffffffffu, slo, o);
            shi += __shfl_xor_sync(0xffffffffu, shi, o);
        }
        if (c0 == 0) {
            psum[w * 64 + R] = slo;
            psum[w * 64 + R + 8] = shi;
        }
#pragma unroll
        for (int nt = 0; nt < NTQ; nt++) {
            int cH2 = (colb >> 1) + nt * 4 + c0;
            __half2 p0 = __floats2half2_rn(acc[mt][nt][0], acc[mt][nt][1]);
            __half2 p1 = __floats2half2_rn(acc[mt][nt][2], acc[mt][nt][3]);
            Pu[R * PS2 + cH2] = *(uint32_t*)&p0;
            Pu[(R + 8) * PS2 + cH2] = *(uint32_t*)&p1;
        }
    }
    __syncthreads();

    // ---- PV (fp16): warp = (row-quarter wr, dim-half sh); P + V via ldmatrix ----
    int wr = w & 3, sh = w >> 2;
    int rowA = wr * 16 + r0;
    uint32_t vbase = smem_u32(smc + VOFF);
    uint32_t lm_base = vbase + ((lane & 7) + 8 * ((lane >> 3) & 1)) * 144
                             + (sh * 32 + 8 * (lane >> 4)) * 2;
    uint32_t pa_addr = smem_u32(smc + KOFF) + (wr * 16 + (lane & 15)) * (PS2 * 4)
                     + (lane >> 4) * 16;

    float oacc[4][4];
#pragma unroll
    for (int nt = 0; nt < 4; nt++)
#pragma unroll
        for (int q = 0; q < 4; q++) oacc[nt][q] = 0.0f;

#pragma unroll 4
    for (int kc = 0; kc < S / 16; kc++) {
        uint32_t a0, a1, a2, a3;
        ldsm_x4(a0, a1, a2, a3, pa_addr + kc * 32);
        uint32_t lmaddr = lm_base + kc * 16 * 144;
#pragma unroll
        for (int ng = 0; ng < 2; ng++) {
            uint32_t b0, b1, b2, b3;
            ldsm_x4_t(b0, b1, b2, b3, lmaddr + ng * 32);
            mma16(oacc[ng * 2], a0, a1, a2, a3, b0, b1);
            mma16(oacc[ng * 2 + 1], a0, a1, a2, a3, b2, b3);
        }
    }

    // ---- epilogue: 1/sum scale, store fp32 ----
    float slo = psum[rowA], shi = psum[rowA + 8];
#pragma unroll
    for (int ww = 1; ww < 8; ww++) {
        slo += psum[ww * 64 + rowA];
        shi += psum[ww * 64 + rowA + 8];
    }
    float rlo = 1.0f / slo, rhi = 1.0f / shi;
#pragma unroll
    for (int nt = 0; nt < 4; nt++) {
        int d = sh * 32 + nt * 8 + c0 * 2;
        float* olo = outp + (size_t)grp * outGroupStride
                   + (size_t)(i0 + rowA) * outPosStride + h * 64 + d;
        float* ohi = outp + (size_t)grp * outGroupStride
                   + (size_t)(i0 + rowA + 8) * outPosStride + h * 64 + d;
        *(float2*)olo = make_float2(oacc[nt][0] * rlo, oacc[nt][1] * rlo);
        *(float2*)ohi = make_float2(oacc[nt][2] * rhi, oacc[nt][3] * rhi);
    }
}

#define ATTN_SMEM(S) (S * 144 * 2 + 64 * 144 + S * 4 + 4096)

// ------------------------- residual + LayerNorm (optional fp16 second output) -------------------------
__global__ __launch_bounds__(256)
void ln_kernel(const float* __restrict__ x, const float* __restrict__ r,
               const float* __restrict__ g, const float* __restrict__ b,
               float* __restrict__ out, __half* __restrict__ cvtout) {
    __shared__ float rs[8], rq[8], sh[2];
    int row = blockIdx.x, tid = threadIdx.x;
    size_t b0 = (size_t)row * DD;
    float v[3]; float s = 0.0f, q = 0.0f;
#pragma unroll
    for (int u = 0; u < 3; u++) {
        int c = tid + u * 256;
        float t = x[b0 + c] + r[b0 + c];
        v[u] = t; s += t; q += t * t;
    }
#pragma unroll
    for (int o = 16; o > 0; o >>= 1) {
        s += __shfl_down_sync(0xffffffffu, s, o);
        q += __shfl_down_sync(0xffffffffu, q, o);
    }
    int wid = tid >> 5, lane = tid & 31;
    if (lane == 0) { rs[wid] = s; rq[wid] = q; }
    __syncthreads();
    if (tid == 0) {
        float S = 0.0f, Q = 0.0f;
#pragma unroll
        for (int w = 0; w < 8; w++) { S += rs[w]; Q += rq[w]; }
        float mu = S * (1.0f / 768.0f);
        sh[0] = mu;
        sh[1] = rsqrtf(Q * (1.0f / 768.0f) - mu * mu + 1e-5f);
    }
    __syncthreads();
    float mu = sh[0], inv = sh[1];
#pragma unroll
    for (int u = 0; u < 3; u++) {
        int c = tid + u * 256;
        float o = (v[u] - mu) * inv * g[c] + b[c];
        out[b0 + c] = o;
        if (cvtout) cvtout[b0 + c] = __float2half_rn(o);
    }
}

// ------------------------- launch -------------------------
extern "C" void kernel_launch(void* const* d_in, const int* in_sizes, int n_in,
                              void* d_out, int out_size) {
    const float* x     = (const float*)d_in[0];
    const float* w_row = (const float*)d_in[1];
    const float* b_row = (const float*)d_in[2];
    const float* w_col = (const float*)d_in[3];
    const float* b_col = (const float*)d_in[4];
    const float* g1    = (const float*)d_in[5];
    const float* be1   = (const float*)d_in[6];
    const float* g2    = (const float*)d_in[7];
    const float* be2   = (const float*)d_in[8];
    const void*  mask  = d_in[9];
    float* out = (float*)d_out;

    float *tmp, *neg;
    __half *qkvh, *acvh, *wcvh;
    cudaGetSymbolAddress((void**)&qkvh, g_qkvh);
    cudaGetSymbolAddress((void**)&tmp, g_tmp);
    cudaGetSymbolAddress((void**)&acvh, g_acvh);
    cudaGetSymbolAddress((void**)&wcvh, g_wcvh);
    cudaGetSymbolAddress((void**)&neg, g_neg);

    cudaFuncSetAttribute(attn_tc_kernel<256>, cudaFuncAttributeMaxDynamicSharedMemorySize, ATTN_SMEM(256));
    cudaFuncSetAttribute(attn_tc_kernel<128>, cudaFuncAttributeMaxDynamicSharedMemorySize, ATTN_SMEM(128));
    cudaFuncSetAttribute(gemm_mma_kernel, cudaFuncAttributeMaxDynamicSharedMemorySize, GEMM_SMEM);

    neg_kernel<<<1, 256>>>(mask);

    dim3 ggrid(D3 / GN, NROWS / GM);   // (18, 256)
    const int ACV_BLKS = (int)(((size_t)NROWS * DD) / 2048);   // 12288
    const int WCV_BLKS = (int)(((size_t)D3 * DD) / 2048);      // 864

    // ---- row attention block ----
    cvt_h_kernel<<<ACV_BLKS, 256>>>(x, acvh);
    cvt_h_kernel<<<WCV_BLKS, 256>>>(w_row, wcvh);
    gemm_mma_kernel<<<ggrid, 256, GEMM_SMEM>>>(acvh, wcvh, b_row, qkvh);
    {
        dim3 agrid(LL / 64, 12, EE);
        attn_tc_kernel<256><<<agrid, 256, ATTN_SMEM(256)>>>(
            qkvh, (long)LL * D3, (long)D3,
            neg, (long)LL, 1L,
            tmp, (long)LL * DD, (long)DD);
    }
    ln_kernel<<<NROWS, 256>>>(x, tmp, g1, be1, out, acvh);   // dual-write: fp32 + fp16

    // ---- column attention block ----
    cvt_h_kernel<<<WCV_BLKS, 256>>>(w_col, wcvh);
    gemm_mma_kernel<<<ggrid, 256, GEMM_SMEM>>>(acvh, wcvh, b_col, qkvh);
    {
        dim3 agrid(EE / 64, 12, LL);
        attn_tc_kernel<128><<<agrid, 256, ATTN_SMEM(128)>>>(
            qkvh, (long)D3, (long)LL * D3,
            neg, 1L, (long)LL,
            tmp, (long)DD, (long)LL * DD);
    }
    ln_kernel<<<NROWS, 256>>>(out, tmp, g2, be2, out, (__half*)0);
}

// round 16
// speedup vs baseline: 1.0539x; 1.0539x over previous
#include <cuda_runtime.h>
#include <cuda_bf16.h>
#include <cuda_fp16.h>
#include <stdint.h>
#include <math.h>

// Problem constants: B=1, E=128, L=256, D=768, H=12, DH=64
#define EE 128
#define LL 256
#define DD 768
#define D3 2304
#define NROWS 32768          // E*L
#define NEGV (-10000.0f)

typedef unsigned long long ull;

// ------------------------- scratch (static device globals; no runtime alloc) -------------------------
__device__ __half g_qkvh[(size_t)NROWS * D3];  // 151 MB (fp16 qkv from GEMM)
__device__ __half g_tmph[(size_t)NROWS * DD];  // 50 MB (fp16 attention output)
__device__ __half g_acvh[(size_t)NROWS * DD];  // 50 MB (fp16 activations)
__device__ __half g_wcvh[(size_t)D3 * DD];     // 3.5 MB (fp16 weights)
__device__ float  g_neg[NROWS];

// ------------------------- PTX helpers -------------------------
__device__ __forceinline__ uint32_t smem_u32(const void* p) {
    uint32_t a;
    asm("{ .reg .u64 t; cvta.to.shared.u64 t, %1; cvt.u32.u64 %0, t; }" : "=r"(a) : "l"(p));
    return a;
}
__device__ __forceinline__ void cp_async16(uint32_t dst, const void* src) {
    asm volatile("cp.async.cg.shared.global [%0], [%1], 16;" :: "r"(dst), "l"(src) : "memory");
}
// fp16 m16n8k16, fp32 accum
__device__ __forceinline__ void mma16(float* c, uint32_t a0, uint32_t a1, uint32_t a2, uint32_t a3,
                                      uint32_t b0, uint32_t b1) {
    asm volatile(
        "mma.sync.aligned.m16n8k16.row.col.f32.f16.f16.f32 "
        "{%0,%1,%2,%3}, {%4,%5,%6,%7}, {%8,%9}, {%0,%1,%2,%3};"
        : "+f"(c[0]), "+f"(c[1]), "+f"(c[2]), "+f"(c[3])
        : "r"(a0), "r"(a1), "r"(a2), "r"(a3), "r"(b0), "r"(b1));
}
__device__ __forceinline__ void ldsm_x4(uint32_t& r0, uint32_t& r1, uint32_t& r2, uint32_t& r3,
                                        uint32_t addr) {
    asm volatile("ldmatrix.sync.aligned.m8n8.x4.shared.b16 {%0,%1,%2,%3}, [%4];"
                 : "=r"(r0), "=r"(r1), "=r"(r2), "=r"(r3) : "r"(addr));
}
__device__ __forceinline__ void ldsm_x4_t(uint32_t& r0, uint32_t& r1, uint32_t& r2, uint32_t& r3,
                                          uint32_t addr) {
    asm volatile("ldmatrix.sync.aligned.m8n8.x4.trans.shared.b16 {%0,%1,%2,%3}, [%4];"
                 : "=r"(r0), "=r"(r1), "=r"(r2), "=r"(r3) : "r"(addr));
}

// ------------------------- padding mask -> additive neg, with dtype auto-detect -------------------------
__global__ void neg_kernel(const void* mraw) {
    __shared__ int notInt, notFloat;
    int tid = threadIdx.x;
    if (tid == 0) { notInt = 0; notFloat = 0; }
    __syncthreads();
    const unsigned int* w = (const unsigned int*)mraw;
    int badI = 0, badF = 0;
    for (int i = tid; i < 8192; i += 256) {
        unsigned int v = w[i];
        if (v > 1u) badI = 1;
        if (v != 0u && v != 0x3F800000u) badF = 1;
    }
    if (badI) notInt = 1;
    if (badF) notFloat = 1;
    __syncthreads();
    int mode = (!notInt) ? 0 : ((!notFloat) ? 1 : 2);  // 0=int32, 1=float32, 2=uint8
    for (int i = tid; i < NROWS; i += 256) {
        bool m;
        if (mode == 0)      m = ((const int*)mraw)[i] != 0;
        else if (mode == 1) m = ((const float*)mraw)[i] != 0.0f;
        else                m = ((const unsigned char*)mraw)[i] != 0;
        g_neg[i] = m ? NEGV : 0.0f;
    }
}

// ------------------------- fp32 -> fp16 pre-pass (8 elements/thread) -------------------------
__global__ __launch_bounds__(256)
void cvt_h_kernel(const float* __restrict__ in, __half* __restrict__ out) {
    size_t i = ((size_t)blockIdx.x * 256 + threadIdx.x) * 8;
    float4 v0 = *(const float4*)(in + i);
    float4 v1 = *(const float4*)(in + i + 4);
    __half2 h0 = __floats2half2_rn(v0.x, v0.y);
    __half2 h1 = __floats2half2_rn(v0.z, v0.w);
    __half2 h2 = __floats2half2_rn(v1.x, v1.y);
    __half2 h3 = __floats2half2_rn(v1.z, v1.w);
    uint4 u;
    u.x = *(uint32_t*)&h0; u.y = *(uint32_t*)&h1;
    u.z = *(uint32_t*)&h2; u.w = *(uint32_t*)&h3;
    *(uint4*)(out + i) = u;
}

// ------------------------- fp16 mma GEMM (unchanged from R14) -------------------------
#define GM 128
#define GN 128
#define KB 32
#define NST 24                       // 768/32
#define KS2 20                       // row stride in half2 units (80 B/row)
#define AU (GM * KS2)
#define BU (GN * KS2)
#define STAGEU (AU + BU)             // 5120 uint32 = 20480 B
#define GEMM_SMEM (3 * STAGEU * 4)   // 61440 bytes

__device__ __forceinline__ void load_stage(uint32_t* smu, int stg, const __half* Ah, const __half* Wh,
                                           int k0, int tid) {
    uint32_t as_u = smem_u32(smu + stg * STAGEU);
    uint32_t bs_u = as_u + AU * 4;
#pragma unroll
    for (int i = 0; i < 2; i++) {
        int idx = tid + i * 256;
        int row = idx >> 2, ch = idx & 3;
        cp_async16(as_u + row * (KS2 * 4) + ch * 16, Ah + (size_t)row * DD + k0 + ch * 8);
    }
#pragma unroll
    for (int i = 0; i < 2; i++) {
        int idx = tid + i * 256;
        int row = idx >> 2, ch = idx & 3;
        cp_async16(bs_u + row * (KS2 * 4) + ch * 16, Wh + (size_t)row * DD + k0 + ch * 8);
    }
}

__global__ __launch_bounds__(256, 2)
void gemm_mma_kernel(const __half* __restrict__ A, const __half* __restrict__ W,
                     const float* __restrict__ bias, __half* __restrict__ C) {
    extern __shared__ uint32_t smu[];
    int tid = threadIdx.x, lane = tid & 31, w = tid >> 5;
    int wm = w & 3, wn = w >> 2;
    int m0 = blockIdx.y * GM, n0 = blockIdx.x * GN;
    const __half* Ah = A + (size_t)m0 * DD;
    const __half* Wh = W + (size_t)n0 * DD;
    int r0 = lane >> 2, c0 = lane & 3;

    uint32_t a_off = (uint32_t)((wm * 32 + (lane & 15)) * 80 + (lane >> 4) * 16);
    uint32_t b_off = (uint32_t)((wn * 64 + ((lane >> 4) & 1) * 8 + (lane & 7)) * 80
                                + ((lane >> 3) & 1) * 16);

    float acc[2][8][4];
#pragma unroll
    for (int mt = 0; mt < 2; mt++)
#pragma unroll
        for (int nt = 0; nt < 8; nt++)
#pragma unroll
            for (int q = 0; q < 4; q++) acc[mt][nt][q] = 0.0f;

    load_stage(smu, 0, Ah, Wh, 0, tid);
    asm volatile("cp.async.commit_group;" ::: "memory");
    load_stage(smu, 1, Ah, Wh, KB, tid);
    asm volatile("cp.async.commit_group;" ::: "memory");

    uint32_t sbase = smem_u32(smu);

    for (int s = 0; s < NST; ++s) {
        int b = s % 3;
        asm volatile("cp.async.wait_group 1;" ::: "memory");
        __syncthreads();
        if (s + 2 < NST) load_stage(smu, (s + 2) % 3, Ah, Wh, (s + 2) * KB, tid);
        asm volatile("cp.async.commit_group;" ::: "memory");

        uint32_t as_u = sbase + b * (STAGEU * 4);
        uint32_t bs_u = as_u + AU * 4;
#pragma unroll
        for (int ks = 0; ks < 2; ks++) {
            uint32_t koff = ks * 32;
            uint32_t bf[8][2];
#pragma unroll
            for (int ntp = 0; ntp < 4; ntp++) {
                uint32_t r0v, r1v, r2v, r3v;
                ldsm_x4(r0v, r1v, r2v, r3v, bs_u + b_off + ntp * (16 * 80) + koff);
                bf[ntp * 2][0] = r0v;     bf[ntp * 2][1] = r1v;
                bf[ntp * 2 + 1][0] = r2v; bf[ntp * 2 + 1][1] = r3v;
            }
#pragma unroll
            for (int mt = 0; mt < 2; mt++) {
                uint32_t a0, a1, a2, a3;
                ldsm_x4(a0, a1, a2, a3, as_u + a_off + mt * (16 * 80) + koff);
#pragma unroll
                for (int nt = 0; nt < 8; nt++)
                    mma16(acc[mt][nt], a0, a1, a2, a3, bf[nt][0], bf[nt][1]);
            }
        }
    }
    asm volatile("cp.async.wait_group 0;" ::: "memory");

#pragma unroll
    for (int nt = 0; nt < 8; nt++) {
        int col = n0 + wn * 64 + nt * 8 + c0 * 2;
        float b0v = bias[col], b1v = bias[col + 1];
#pragma unroll
        for (int mt = 0; mt < 2; mt++) {
            int row = m0 + wm * 32 + mt * 16 + r0;
            __half2 h0 = __floats2half2_rn(acc[mt][nt][0] + b0v, acc[mt][nt][1] + b1v);
            __half2 h1 = __floats2half2_rn(acc[mt][nt][2] + b0v, acc[mt][nt][3] + b1v);
            *(uint32_t*)&C[(size_t)row * D3 + col] = *(uint32_t*)&h0;
            *(uint32_t*)&C[(size_t)(row + 8) * D3 + col] = *(uint32_t*)&h1;
        }
    }
}

// ------------------------- fp16 tensor-core attention (R14 version; fp16 output) -------------------------
#define HSTR 36      // half2 stride for Q/K/V rows

template<int S>
__global__ __launch_bounds__(256, 2)
void attn_tc_kernel(const __half* __restrict__ qkv,
                    long groupStride, long posStride,
                    const float* __restrict__ neg, long negGroupStride, long negStride,
                    __half* __restrict__ outp, long outGroupStride, long outPosStride) {
    constexpr int PS2 = S / 2 + 4;
    constexpr int CW = S / 8;
    constexpr int NTQ = CW / 8;
    constexpr int VOFF = 0;
    constexpr int KOFF = VOFF + S * 144;
    constexpr int QOFF = KOFF + S * 144;
    constexpr int NOFF = QOFF + 64 * 144;
    constexpr int MOFF = NOFF + S * 4;
    extern __shared__ char smc[];
    float* negs = (float*)(smc + NOFF);
    float* pmax = (float*)(smc + MOFF);
    float* psum = (float*)(smc + MOFF + 2048);

    int h   = blockIdx.y;
    int grp = blockIdx.z;
    int i0  = blockIdx.x * 64;
    const __half* base = qkv + (size_t)grp * groupStride;
    const __half* qb = base + h * 64;
    const __half* kb = base + 768 + h * 64;
    const __half* vb = base + 1536 + h * 64;
    int tid = threadIdx.x;

    for (int idx = tid; idx < S * 8; idx += 256) {
        int j = idx >> 3, c8 = idx & 7;
        uint4 kv4 = *(const uint4*)(kb + (size_t)j * posStride + c8 * 8);
        uint4 vv4 = *(const uint4*)(vb + (size_t)j * posStride + c8 * 8);
        *(uint4*)(smc + KOFF + j * 144 + c8 * 16) = kv4;
        *(uint4*)(smc + VOFF + j * 144 + c8 * 16) = vv4;
    }
    {
        __half2 sc = __floats2half2_rn(0.125f, 0.125f);
        for (int idx = tid; idx < 64 * 8; idx += 256) {
            int i = idx >> 3, c8 = idx & 7;
            uint4 q4 = *(const uint4*)(qb + (size_t)(i0 + i) * posStride + c8 * 8);
            __half2* qh = (__half2*)&q4;
            qh[0] = __hmul2(qh[0], sc); qh[1] = __hmul2(qh[1], sc);
            qh[2] = __hmul2(qh[2], sc); qh[3] = __hmul2(qh[3], sc);
            *(uint4*)(smc + QOFF + i * 144 + c8 * 16) = q4;
        }
    }
    if (tid < S) negs[tid] = neg[(size_t)grp * negGroupStride + (size_t)tid * negStride];
    __syncthreads();

    int w = tid >> 5, lane = tid & 31;
    int r0 = lane >> 2, c0 = lane & 3;
    int colb = w * CW;

    const uint32_t* Qu = (const uint32_t*)(smc + QOFF);
    const uint32_t* Ku = (const uint32_t*)(smc + KOFF);

    float acc[4][NTQ][4];
#pragma unroll
    for (int mt = 0; mt < 4; mt++)
#pragma unroll
        for (int nt = 0; nt < NTQ; nt++)
#pragma unroll
            for (int q = 0; q < 4; q++) acc[mt][nt][q] = 0.0f;

#pragma unroll
    for (int kc = 0; kc < 4; kc++) {
        int K0 = kc * 8 + c0;
        uint32_t bfr[NTQ][2];
#pragma unroll
        for (int nt = 0; nt < NTQ; nt++) {
            int j = colb + nt * 8 + r0;
            bfr[nt][0] = Ku[j * HSTR + K0];
            bfr[nt][1] = Ku[j * HSTR + K0 + 4];
        }
#pragma unroll
        for (int mt = 0; mt < 4; mt++) {
            int R = mt * 16 + r0;
            uint32_t a0 = Qu[R * HSTR + K0];
            uint32_t a1 = Qu[(R + 8) * HSTR + K0];
            uint32_t a2 = Qu[R * HSTR + K0 + 4];
            uint32_t a3 = Qu[(R + 8) * HSTR + K0 + 4];
#pragma unroll
            for (int nt = 0; nt < NTQ; nt++)
                mma16(acc[mt][nt], a0, a1, a2, a3, bfr[nt][0], bfr[nt][1]);
        }
    }

    float mlo[4], mhi[4];
#pragma unroll
    for (int mt = 0; mt < 4; mt++) { mlo[mt] = -3.4e38f; mhi[mt] = -3.4e38f; }
#pragma unroll
    for (int nt = 0; nt < NTQ; nt++) {
        int cA = colb + nt * 8 + c0 * 2;
        float n0v = negs[cA], n1v = negs[cA + 1];
#pragma unroll
        for (int mt = 0; mt < 4; mt++) {
            acc[mt][nt][0] += n0v; acc[mt][nt][1] += n1v;
            acc[mt][nt][2] += n0v; acc[mt][nt][3] += n1v;
            mlo[mt] = fmaxf(mlo[mt], fmaxf(acc[mt][nt][0], acc[mt][nt][1]));
            mhi[mt] = fmaxf(mhi[mt], fmaxf(acc[mt][nt][2], acc[mt][nt][3]));
        }
    }
#pragma unroll
    for (int mt = 0; mt < 4; mt++) {
#pragma unroll
        for (int o = 1; o <= 2; o <<= 1) {
            mlo[mt] = fmaxf(mlo[mt], __shfl_xor_sync(0xffffffffu, mlo[mt], o));
            mhi[mt] = fmaxf(mhi[mt], __shfl_xor_sync(0xffffffffu, mhi[mt], o));
        }
        if (c0 == 0) {
            pmax[w * 64 + mt * 16 + r0] = mlo[mt];
            pmax[w * 64 + mt * 16 + r0 + 8] = mhi[mt];
        }
    }
    __syncthreads();

    uint32_t* Pu = (uint32_t*)(smc + KOFF);
#pragma unroll
    for (int mt = 0; mt < 4; mt++) {
        int R = mt * 16 + r0;
        float gmlo = pmax[R], gmhi = pmax[R + 8];
#pragma unroll
        for (int ww = 1; ww < 8; ww++) {
            gmlo = fmaxf(gmlo, pmax[ww * 64 + R]);
            gmhi = fmaxf(gmhi, pmax[ww * 64 + R + 8]);
        }
        float slo = 0.0f, shi = 0.0f;
#pragma unroll
        for (int nt = 0; nt < NTQ; nt++) {
            acc[mt][nt][0] = __expf(acc[mt][nt][0] - gmlo);
            acc[mt][nt][1] = __expf(acc[mt][nt][1] - gmlo);
            acc[mt][nt][2] = __expf(acc[mt][nt][2] - gmhi);
            acc[mt][nt][3] = __expf(acc[mt][nt][3] - gmhi);
            slo += acc[mt][nt][0] + acc[mt][nt][1];
            shi += acc[mt][nt][2] + acc[mt][nt][3];
        }
#pragma unroll
        for (int o = 1; o <= 2; o <<= 1) {
            slo += __shfl_xor_sync(0xffffffffu, slo, o);
            shi += __shfl_xor_sync(0xffffffffu, shi, o);
        }
        if (c0 == 0) {
            psum[w * 64 + R] = slo;
            psum[w * 64 + R + 8] = shi;
        }
#pragma unroll
        for (int nt = 0; nt < NTQ; nt++) {
            int cH2 = (colb >> 1) + nt * 4 + c0;
            __half2 p0 = __floats2half2_rn(acc[mt][nt][0], acc[mt][nt][1]);
            __half2 p1 = __floats2half2_rn(acc[mt][nt][2], acc[mt][nt][3]);
            Pu[R * PS2 + cH2] = *(uint32_t*)&p0;
            Pu[(R + 8) * PS2 + cH2] = *(uint32_t*)&p1;
        }
    }
    __syncthreads();

    int wr = w & 3, sh = w >> 2;
    int rowA = wr * 16 + r0;
    uint32_t vbase = smem_u32(smc + VOFF);
    uint32_t lm_base = vbase + ((lane & 7) + 8 * ((lane >> 3) & 1)) * 144
                             + (sh * 32 + 8 * (lane >> 4)) * 2;

    float oacc[4][4];
#pragma unroll
    for (int nt = 0; nt < 4; nt++)
#pragma unroll
        for (int q = 0; q < 4; q++) oacc[nt][q] = 0.0f;

#pragma unroll 4
    for (int kc = 0; kc < S / 16; kc++) {
        int K0 = kc * 8 + c0;
        uint32_t a0 = Pu[rowA * PS2 + K0];
        uint32_t a1 = Pu[(rowA + 8) * PS2 + K0];
        uint32_t a2 = Pu[rowA * PS2 + K0 + 4];
        uint32_t a3 = Pu[(rowA + 8) * PS2 + K0 + 4];
        uint32_t lmaddr = lm_base + kc * 16 * 144;
#pragma unroll
        for (int ng = 0; ng < 2; ng++) {
            uint32_t b0, b1, b2, b3;
            ldsm_x4_t(b0, b1, b2, b3, lmaddr + ng * 32);
            mma16(oacc[ng * 2], a0, a1, a2, a3, b0, b1);
            mma16(oacc[ng * 2 + 1], a0, a1, a2, a3, b2, b3);
        }
    }

    float slo = psum[rowA], shi = psum[rowA + 8];
#pragma unroll
    for (int ww = 1; ww < 8; ww++) {
        slo += psum[ww * 64 + rowA];
        shi += psum[ww * 64 + rowA + 8];
    }
    float rlo = 1.0f / slo, rhi = 1.0f / shi;
#pragma unroll
    for (int nt = 0; nt < 4; nt++) {
        int d = sh * 32 + nt * 8 + c0 * 2;
        __half* olo = outp + (size_t)grp * outGroupStride
                    + (size_t)(i0 + rowA) * outPosStride + h * 64 + d;
        __half* ohi = outp + (size_t)grp * outGroupStride
                    + (size_t)(i0 + rowA + 8) * outPosStride + h * 64 + d;
        __half2 v0 = __floats2half2_rn(oacc[nt][0] * rlo, oacc[nt][1] * rlo);
        __half2 v1 = __floats2half2_rn(oacc[nt][2] * rhi, oacc[nt][3] * rhi);
        *(uint32_t*)olo = *(uint32_t*)&v0;
        *(uint32_t*)ohi = *(uint32_t*)&v1;
    }
}

#define ATTN_SMEM(S) (S * 144 * 2 + 64 * 144 + S * 4 + 4096)

// ------------------------- residual + LayerNorm (fp16 residual input; optional fp16 second output) ----
__global__ __launch_bounds__(256)
void ln_kernel(const float* __restrict__ x, const __half* __restrict__ r,
               const float* __restrict__ g, const float* __restrict__ b,
               float* __restrict__ out, __half* __restrict__ cvtout) {
    __shared__ float rs[8], rq[8], sh[2];
    int row = blockIdx.x, tid = threadIdx.x;
    size_t b0 = (size_t)row * DD;
    float v[3]; float s = 0.0f, q = 0.0f;
#pragma unroll
    for (int u = 0; u < 3; u++) {
        int c = tid + u * 256;
        float t = x[b0 + c] + __half2float(r[b0 + c]);
        v[u] = t; s += t; q += t * t;
    }
#pragma unroll
    for (int o = 16; o > 0; o >>= 1) {
        s += __shfl_down_sync(0xffffffffu, s, o);
        q += __shfl_down_sync(0xffffffffu, q, o);
    }
    int wid = tid >> 5, lane = tid & 31;
    if (lane == 0) { rs[wid] = s; rq[wid] = q; }
    __syncthreads();
    if (tid == 0) {
        float S = 0.0f, Q = 0.0f;
#pragma unroll
        for (int w = 0; w < 8; w++) { S += rs[w]; Q += rq[w]; }
        float mu = S * (1.0f / 768.0f);
        sh[0] = mu;
        sh[1] = rsqrtf(Q * (1.0f / 768.0f) - mu * mu + 1e-5f);
    }
    __syncthreads();
    float mu = sh[0], inv = sh[1];
#pragma unroll
    for (int u = 0; u < 3; u++) {
        int c = tid + u * 256;
        float o = (v[u] - mu) * inv * g[c] + b[c];
        out[b0 + c] = o;
        if (cvtout) cvtout[b0 + c] = __float2half_rn(o);
    }
}

// ------------------------- launch -------------------------
extern "C" void kernel_launch(void* const* d_in, const int* in_sizes, int n_in,
                              void* d_out, int out_size) {
    const float* x     = (const float*)d_in[0];
    const float* w_row = (const float*)d_in[1];
    const float* b_row = (const float*)d_in[2];
    const float* w_col = (const float*)d_in[3];
    const float* b_col = (const float*)d_in[4];
    const float* g1    = (const float*)d_in[5];
    const float* be1   = (const float*)d_in[6];
    const float* g2    = (const float*)d_in[7];
    const float* be2   = (const float*)d_in[8];
    const void*  mask  = d_in[9];
    float* out = (float*)d_out;

    float *neg;
    __half *qkvh, *tmph, *acvh, *wcvh;
    cudaGetSymbolAddress((void**)&qkvh, g_qkvh);
    cudaGetSymbolAddress((void**)&tmph, g_tmph);
    cudaGetSymbolAddress((void**)&acvh, g_acvh);
    cudaGetSymbolAddress((void**)&wcvh, g_wcvh);
    cudaGetSymbolAddress((void**)&neg, g_neg);

    cudaFuncSetAttribute(attn_tc_kernel<256>, cudaFuncAttributeMaxDynamicSharedMemorySize, ATTN_SMEM(256));
    cudaFuncSetAttribute(attn_tc_kernel<128>, cudaFuncAttributeMaxDynamicSharedMemorySize, ATTN_SMEM(128));
    cudaFuncSetAttribute(gemm_mma_kernel, cudaFuncAttributeMaxDynamicSharedMemorySize, GEMM_SMEM);

    neg_kernel<<<1, 256>>>(mask);

    dim3 ggrid(D3 / GN, NROWS / GM);   // (18, 256)
    const int ACV_BLKS = (int)(((size_t)NROWS * DD) / 2048);   // 12288
    const int WCV_BLKS = (int)(((size_t)D3 * DD) / 2048);      // 864

    // ---- row attention block ----
    cvt_h_kernel<<<ACV_BLKS, 256>>>(x, acvh);
    cvt_h_kernel<<<WCV_BLKS, 256>>>(w_row, wcvh);
    gemm_mma_kernel<<<ggrid, 256, GEMM_SMEM>>>(acvh, wcvh, b_row, qkvh);
    {
        dim3 agrid(LL / 64, 12, EE);
        attn_tc_kernel<256><<<agrid, 256, ATTN_SMEM(256)>>>(
            qkvh, (long)LL * D3, (long)D3,
            neg, (long)LL, 1L,
            tmph, (long)LL * DD, (long)DD);
    }
    ln_kernel<<<NROWS, 256>>>(x, tmph, g1, be1, out, acvh);   // dual-write: fp32 + fp16

    // ---- column attention block ----
    cvt_h_kernel<<<WCV_BLKS, 256>>>(w_col, wcvh);
    gemm_mma_kernel<<<ggrid, 256, GEMM_SMEM>>>(acvh, wcvh, b_col, qkvh);
    {
        dim3 agrid(EE / 64, 12, LL);
        attn_tc_kernel<128><<<agrid, 256, ATTN_SMEM(128)>>>(
            qkvh, (long)D3, (long)LL * D3,
            neg, 1L, (long)LL,
            tmph, (long)DD, (long)LL * DD);
    }
    ln_kernel<<<NROWS, 256>>>(out, tmph, g2, be2, out, (__half*)0);
}

// round 17
// speedup vs baseline: 1.0646x; 1.0101x over previous
#include <cuda_runtime.h>
#include <cuda_bf16.h>
#include <cuda_fp16.h>
#include <stdint.h>
#include <math.h>

// Problem constants: B=1, E=128, L=256, D=768, H=12, DH=64
#define EE 128
#define LL 256
#define DD 768
#define D3 2304
#define NROWS 32768          // E*L
#define NEGV (-10000.0f)

typedef unsigned long long ull;

// ------------------------- scratch (static device globals; no runtime alloc) -------------------------
__device__ __half g_qkvh[(size_t)NROWS * D3];  // 151 MB (fp16 qkv from GEMM)
__device__ __half g_tmph[(size_t)NROWS * DD];  // 50 MB (fp16 attention output)
__device__ __half g_acvh[(size_t)NROWS * DD];  // 50 MB (fp16 activations)
__device__ __half g_wcvh[(size_t)D3 * DD];     // 3.5 MB (fp16 weights)
__device__ float  g_neg[NROWS];

// ------------------------- PTX helpers -------------------------
__device__ __forceinline__ uint32_t smem_u32(const void* p) {
    uint32_t a;
    asm("{ .reg .u64 t; cvta.to.shared.u64 t, %1; cvt.u32.u64 %0, t; }" : "=r"(a) : "l"(p));
    return a;
}
__device__ __forceinline__ void cp_async16(uint32_t dst, const void* src) {
    asm volatile("cp.async.cg.shared.global [%0], [%1], 16;" :: "r"(dst), "l"(src) : "memory");
}
// fp16 m16n8k16, fp32 accum
__device__ __forceinline__ void mma16(float* c, uint32_t a0, uint32_t a1, uint32_t a2, uint32_t a3,
                                      uint32_t b0, uint32_t b1) {
    asm volatile(
        "mma.sync.aligned.m16n8k16.row.col.f32.f16.f16.f32 "
        "{%0,%1,%2,%3}, {%4,%5,%6,%7}, {%8,%9}, {%0,%1,%2,%3};"
        : "+f"(c[0]), "+f"(c[1]), "+f"(c[2]), "+f"(c[3])
        : "r"(a0), "r"(a1), "r"(a2), "r"(a3), "r"(b0), "r"(b1));
}
__device__ __forceinline__ void ldsm_x4(uint32_t& r0, uint32_t& r1, uint32_t& r2, uint32_t& r3,
                                        uint32_t addr) {
    asm volatile("ldmatrix.sync.aligned.m8n8.x4.shared.b16 {%0,%1,%2,%3}, [%4];"
                 : "=r"(r0), "=r"(r1), "=r"(r2), "=r"(r3) : "r"(addr));
}
__device__ __forceinline__ void ldsm_x4_t(uint32_t& r0, uint32_t& r1, uint32_t& r2, uint32_t& r3,
                                          uint32_t addr) {
    asm volatile("ldmatrix.sync.aligned.m8n8.x4.trans.shared.b16 {%0,%1,%2,%3}, [%4];"
                 : "=r"(r0), "=r"(r1), "=r"(r2), "=r"(r3) : "r"(addr));
}

// ------------------------- padding mask -> additive neg, with dtype auto-detect -------------------------
__global__ void neg_kernel(const void* mraw) {
    __shared__ int notInt, notFloat;
    int tid = threadIdx.x;
    if (tid == 0) { notInt = 0; notFloat = 0; }
    __syncthreads();
    const unsigned int* w = (const unsigned int*)mraw;
    int badI = 0, badF = 0;
    for (int i = tid; i < 8192; i += 256) {
        unsigned int v = w[i];
        if (v > 1u) badI = 1;
        if (v != 0u && v != 0x3F800000u) badF = 1;
    }
    if (badI) notInt = 1;
    if (badF) notFloat = 1;
    __syncthreads();
    int mode = (!notInt) ? 0 : ((!notFloat) ? 1 : 2);  // 0=int32, 1=float32, 2=uint8
    for (int i = tid; i < NROWS; i += 256) {
        bool m;
        if (mode == 0)      m = ((const int*)mraw)[i] != 0;
        else if (mode == 1) m = ((const float*)mraw)[i] != 0.0f;
        else                m = ((const unsigned char*)mraw)[i] != 0;
        g_neg[i] = m ? NEGV : 0.0f;
    }
}

// ------------------------- fp32 -> fp16 pre-pass (8 elements/thread) -------------------------
__global__ __launch_bounds__(256)
void cvt_h_kernel(const float* __restrict__ in, __half* __restrict__ out) {
    size_t i = ((size_t)blockIdx.x * 256 + threadIdx.x) * 8;
    float4 v0 = *(const float4*)(in + i);
    float4 v1 = *(const float4*)(in + i + 4);
    __half2 h0 = __floats2half2_rn(v0.x, v0.y);
    __half2 h1 = __floats2half2_rn(v0.z, v0.w);
    __half2 h2 = __floats2half2_rn(v1.x, v1.y);
    __half2 h3 = __floats2half2_rn(v1.z, v1.w);
    uint4 u;
    u.x = *(uint32_t*)&h0; u.y = *(uint32_t*)&h1;
    u.z = *(uint32_t*)&h2; u.w = *(uint32_t*)&h3;
    *(uint4*)(out + i) = u;
}

// ------------------------- fp16 mma GEMM: C[M,2304] = A[M,768] @ W[2304,768]^T + bias (fp16 out) ----
// CTA 256 thr (8 warps: 4m x 2n), tile 128x128, warp tile 32x64, K stage 64,
// 3-stage cp.async, ldmatrix fragments, smem-staged coalesced epilogue. 2 CTAs/SM.
#define GM 128
#define GN 128
#define KB 64
#define NST 12                       // 768/64
#define KS2 36                       // row stride in half2 units (144 B/row)
#define AU (GM * KS2)                // 4608 u32
#define BU (GN * KS2)                // 4608 u32
#define STAGEU (AU + BU)             // 9216 u32 = 36864 B
#define GEMM_SMEM (3 * STAGEU * 4)   // 110592 bytes

__device__ __forceinline__ void load_stage(uint32_t* smu, int stg, const __half* Ah, const __half* Wh,
                                           int k0, int tid) {
    uint32_t as_u = smem_u32(smu + stg * STAGEU);
    uint32_t bs_u = as_u + AU * 4;
#pragma unroll
    for (int i = 0; i < 4; i++) {            // A: 128 rows x 8 chunks of 16B (128B/row)
        int idx = tid + i * 256;
        int row = idx >> 3, ch = idx & 7;
        cp_async16(as_u + row * 144 + ch * 16, Ah + (size_t)row * DD + k0 + ch * 8);
    }
#pragma unroll
    for (int i = 0; i < 4; i++) {            // B: 128 rows x 8 chunks
        int idx = tid + i * 256;
        int row = idx >> 3, ch = idx & 7;
        cp_async16(bs_u + row * 144 + ch * 16, Wh + (size_t)row * DD + k0 + ch * 8);
    }
}

__global__ __launch_bounds__(256, 2)
void gemm_mma_kernel(const __half* __restrict__ A, const __half* __restrict__ W,
                     const float* __restrict__ bias, __half* __restrict__ C) {
    extern __shared__ uint32_t smu[];
    int tid = threadIdx.x, lane = tid & 31, w = tid >> 5;
    int wm = w & 3, wn = w >> 2;              // warp grid 4 (m, 32 rows) x 2 (n, 64 cols)
    int m0 = blockIdx.y * GM, n0 = blockIdx.x * GN;
    const __half* Ah = A + (size_t)m0 * DD;
    const __half* Wh = W + (size_t)n0 * DD;
    int r0 = lane >> 2, c0 = lane & 3;

    uint32_t a_off = (uint32_t)((wm * 32 + (lane & 15)) * 144 + (lane >> 4) * 16);
    uint32_t b_off = (uint32_t)((wn * 64 + ((lane >> 4) & 1) * 8 + (lane & 7)) * 144
                                + ((lane >> 3) & 1) * 16);

    float acc[2][8][4];
#pragma unroll
    for (int mt = 0; mt < 2; mt++)
#pragma unroll
        for (int nt = 0; nt < 8; nt++)
#pragma unroll
            for (int q = 0; q < 4; q++) acc[mt][nt][q] = 0.0f;

    load_stage(smu, 0, Ah, Wh, 0, tid);
    asm volatile("cp.async.commit_group;" ::: "memory");
    load_stage(smu, 1, Ah, Wh, KB, tid);
    asm volatile("cp.async.commit_group;" ::: "memory");

    uint32_t sbase = smem_u32(smu);

    for (int s = 0; s < NST; ++s) {
        int b = s % 3;
        asm volatile("cp.async.wait_group 1;" ::: "memory");
        __syncthreads();
        if (s + 2 < NST) load_stage(smu, (s + 2) % 3, Ah, Wh, (s + 2) * KB, tid);
        asm volatile("cp.async.commit_group;" ::: "memory");

        uint32_t as_u = sbase + b * (STAGEU * 4);
        uint32_t bs_u = as_u + AU * 4;
#pragma unroll
        for (int ks = 0; ks < 4; ks++) {      // 4 x (K=16) per 64-K stage
            uint32_t koff = ks * 32;
            uint32_t bf[8][2];
#pragma unroll
            for (int ntp = 0; ntp < 4; ntp++) {
                uint32_t r0v, r1v, r2v, r3v;
                ldsm_x4(r0v, r1v, r2v, r3v, bs_u + b_off + ntp * (16 * 144) + koff);
                bf[ntp * 2][0] = r0v;     bf[ntp * 2][1] = r1v;
                bf[ntp * 2 + 1][0] = r2v; bf[ntp * 2 + 1][1] = r3v;
            }
#pragma unroll
            for (int mt = 0; mt < 2; mt++) {
                uint32_t a0, a1, a2, a3;
                ldsm_x4(a0, a1, a2, a3, as_u + a_off + mt * (16 * 144) + koff);
#pragma unroll
                for (int nt = 0; nt < 8; nt++)
                    mma16(acc[mt][nt], a0, a1, a2, a3, bf[nt][0], bf[nt][1]);
            }
        }
    }
    asm volatile("cp.async.wait_group 0;" ::: "memory");
    __syncthreads();    // all smem reads done before staging C

    // ---- epilogue: stage C (fp16 + bias) in smem, then coalesced 16B stores ----
    uint32_t* Cs = smu;   // 128 rows x 68 u32 stride (272B) = 34.8 KB
#pragma unroll
    for (int nt = 0; nt < 8; nt++) {
        int colw = wn * 32 + nt * 4 + c0;         // half2 word col
        int col  = n0 + wn * 64 + nt * 8 + c0 * 2;
        float b0v = bias[col], b1v = bias[col + 1];
#pragma unroll
        for (int mt = 0; mt < 2; mt++) {
            int row = wm * 32 + mt * 16 + r0;
            __half2 h0 = __floats2half2_rn(acc[mt][nt][0] + b0v, acc[mt][nt][1] + b1v);
            __half2 h1 = __floats2half2_rn(acc[mt][nt][2] + b0v, acc[mt][nt][3] + b1v);
            Cs[row * 68 + colw] = *(uint32_t*)&h0;
            Cs[(row + 8) * 68 + colw] = *(uint32_t*)&h1;
        }
    }
    __syncthreads();
#pragma unroll
    for (int i = 0; i < 8; i++) {
        int idx = tid + i * 256;
        int row = idx >> 4, ch = idx & 15;
        uint4 v = *(uint4*)&Cs[row * 68 + ch * 4];
        *(uint4*)&C[(size_t)(m0 + row) * D3 + n0 + ch * 8] = v;
    }
}

// ------------------------- fp16 tensor-core attention (unchanged from R16) -------------------------
#define HSTR 36      // half2 stride for Q/K/V rows

template<int S>
__global__ __launch_bounds__(256, 2)
void attn_tc_kernel(const __half* __restrict__ qkv,
                    long groupStride, long posStride,
                    const float* __restrict__ neg, long negGroupStride, long negStride,
                    __half* __restrict__ outp, long outGroupStride, long outPosStride) {
    constexpr int PS2 = S / 2 + 4;
    constexpr int CW = S / 8;
    constexpr int NTQ = CW / 8;
    constexpr int VOFF = 0;
    constexpr int KOFF = VOFF + S * 144;
    constexpr int QOFF = KOFF + S * 144;
    constexpr int NOFF = QOFF + 64 * 144;
    constexpr int MOFF = NOFF + S * 4;
    extern __shared__ char smc[];
    float* negs = (float*)(smc + NOFF);
    float* pmax = (float*)(smc + MOFF);
    float* psum = (float*)(smc + MOFF + 2048);

    int h   = blockIdx.y;
    int grp = blockIdx.z;
    int i0  = blockIdx.x * 64;
    const __half* base = qkv + (size_t)grp * groupStride;
    const __half* qb = base + h * 64;
    const __half* kb = base + 768 + h * 64;
    const __half* vb = base + 1536 + h * 64;
    int tid = threadIdx.x;

    for (int idx = tid; idx < S * 8; idx += 256) {
        int j = idx >> 3, c8 = idx & 7;
        uint4 kv4 = *(const uint4*)(kb + (size_t)j * posStride + c8 * 8);
        uint4 vv4 = *(const uint4*)(vb + (size_t)j * posStride + c8 * 8);
        *(uint4*)(smc + KOFF + j * 144 + c8 * 16) = kv4;
        *(uint4*)(smc + VOFF + j * 144 + c8 * 16) = vv4;
    }
    {
        __half2 sc = __floats2half2_rn(0.125f, 0.125f);
        for (int idx = tid; idx < 64 * 8; idx += 256) {
            int i = idx >> 3, c8 = idx & 7;
            uint4 q4 = *(const uint4*)(qb + (size_t)(i0 + i) * posStride + c8 * 8);
            __half2* qh = (__half2*)&q4;
            qh[0] = __hmul2(qh[0], sc); qh[1] = __hmul2(qh[1], sc);
            qh[2] = __hmul2(qh[2], sc); qh[3] = __hmul2(qh[3], sc);
            *(uint4*)(smc + QOFF + i * 144 + c8 * 16) = q4;
        }
    }
    if (tid < S) negs[tid] = neg[(size_t)grp * negGroupStride + (size_t)tid * negStride];
    __syncthreads();

    int w = tid >> 5, lane = tid & 31;
    int r0 = lane >> 2, c0 = lane & 3;
    int colb = w * CW;

    const uint32_t* Qu = (const uint32_t*)(smc + QOFF);
    const uint32_t* Ku = (const uint32_t*)(smc + KOFF);

    float acc[4][NTQ][4];
#pragma unroll
    for (int mt = 0; mt < 4; mt++)
#pragma unroll
        for (int nt = 0; nt < NTQ; nt++)
#pragma unroll
            for (int q = 0; q < 4; q++) acc[mt][nt][q] = 0.0f;

#pragma unroll
    for (int kc = 0; kc < 4; kc++) {
        int K0 = kc * 8 + c0;
        uint32_t bfr[NTQ][2];
#pragma unroll
        for (int nt = 0; nt < NTQ; nt++) {
            int j = colb + nt * 8 + r0;
            bfr[nt][0] = Ku[j * HSTR + K0];
            bfr[nt][1] = Ku[j * HSTR + K0 + 4];
        }
#pragma unroll
        for (int mt = 0; mt < 4; mt++) {
            int R = mt * 16 + r0;
            uint32_t a0 = Qu[R * HSTR + K0];
            uint32_t a1 = Qu[(R + 8) * HSTR + K0];
            uint32_t a2 = Qu[R * HSTR + K0 + 4];
            uint32_t a3 = Qu[(R + 8) * HSTR + K0 + 4];
#pragma unroll
            for (int nt = 0; nt < NTQ; nt++)
                mma16(acc[mt][nt], a0, a1, a2, a3, bfr[nt][0], bfr[nt][1]);
        }
    }

    float mlo[4], mhi[4];
#pragma unroll
    for (int mt = 0; mt < 4; mt++) { mlo[mt] = -3.4e38f; mhi[mt] = -3.4e38f; }
#pragma unroll
    for (int nt = 0; nt < NTQ; nt++) {
        int cA = colb + nt * 8 + c0 * 2;
        float n0v = negs[cA], n1v = negs[cA + 1];
#pragma unroll
        for (int mt = 0; mt < 4; mt++) {
            acc[mt][nt][0] += n0v; acc[mt][nt][1] += n1v;
            acc[mt][nt][2] += n0v; acc[mt][nt][3] += n1v;
            mlo[mt] = fmaxf(mlo[mt], fmaxf(acc[mt][nt][0], acc[mt][nt][1]));
            mhi[mt] = fmaxf(mhi[mt], fmaxf(acc[mt][nt][2], acc[mt][nt][3]));
        }
    }
#pragma unroll
    for (int mt = 0; mt < 4; mt++) {
#pragma unroll
        for (int o = 1; o <= 2; o <<= 1) {
            mlo[mt] = fmaxf(mlo[mt], __shfl_xor_sync(0xffffffffu, mlo[mt], o));
            mhi[mt] = fmaxf(mhi[mt], __shfl_xor_sync(0xffffffffu, mhi[mt], o));
        }
        if (c0 == 0) {
            pmax[w * 64 + mt * 16 + r0] = mlo[mt];
            pmax[w * 64 + mt * 16 + r0 + 8] = mhi[mt];
        }
    }
    __syncthreads();

    uint32_t* Pu = (uint32_t*)(smc + KOFF);
#pragma unroll
    for (int mt = 0; mt < 4; mt++) {
        int R = mt * 16 + r0;
        float gmlo = pmax[R], gmhi = pmax[R + 8];
#pragma unroll
        for (int ww = 1; ww < 8; ww++) {
            gmlo = fmaxf(gmlo, pmax[ww * 64 + R]);
            gmhi = fmaxf(gmhi, pmax[ww * 64 + R + 8]);
        }
        float slo = 0.0f, shi = 0.0f;
#pragma unroll
        for (int nt = 0; nt < NTQ; nt++) {
            acc[mt][nt][0] = __expf(acc[mt][nt][0] - gmlo);
            acc[mt][nt][1] = __expf(acc[mt][nt][1] - gmlo);
            acc[mt][nt][2] = __expf(acc[mt][nt][2] - gmhi);
            acc[mt][nt][3] = __expf(acc[mt][nt][3] - gmhi);
            slo += acc[mt][nt][0] + acc[mt][nt][1];
            shi += acc[mt][nt][2] + acc[mt][nt][3];
        }
#pragma unroll
        for (int o = 1; o <= 2; o <<= 1) {
            slo += __shfl_xor_sync(0xffffffffu, slo, o);
            shi += __shfl_xor_sync(0xffffffffu, shi, o);
        }
        if (c0 == 0) {
            psum[w * 64 + R] = slo;
            psum[w * 64 + R + 8] = shi;
        }
#pragma unroll
        for (int nt = 0; nt < NTQ; nt++) {
            int cH2 = (colb >> 1) + nt * 4 + c0;
            __half2 p0 = __floats2half2_rn(acc[mt][nt][0], acc[mt][nt][1]);
            __half2 p1 = __floats2half2_rn(acc[mt][nt][2], acc[mt][nt][3]);
            Pu[R * PS2 + cH2] = *(uint32_t*)&p0;
            Pu[(R + 8) * PS2 + cH2] = *(uint32_t*)&p1;
        }
    }
    __syncthreads();

    int wr = w & 3, sh = w >> 2;
    int rowA = wr * 16 + r0;
    uint32_t vbase = smem_u32(smc + VOFF);
    uint32_t lm_base = vbase + ((lane & 7) + 8 * ((lane >> 3) & 1)) * 144
                             + (sh * 32 + 8 * (lane >> 4)) * 2;

    float oacc[4][4];
#pragma unroll
    for (int nt = 0; nt < 4; nt++)
#pragma unroll
        for (int q = 0; q < 4; q++) oacc[nt][q] = 0.0f;

#pragma unroll 4
    for (int kc = 0; kc < S / 16; kc++) {
        int K0 = kc * 8 + c0;
        uint32_t a0 = Pu[rowA * PS2 + K0];
        uint32_t a1 = Pu[(rowA + 8) * PS2 + K0];
        uint32_t a2 = Pu[rowA * PS2 + K0 + 4];
        uint32_t a3 = Pu[(rowA + 8) * PS2 + K0 + 4];
        uint32_t lmaddr = lm_base + kc * 16 * 144;
#pragma unroll
        for (int ng = 0; ng < 2; ng++) {
            uint32_t b0, b1, b2, b3;
            ldsm_x4_t(b0, b1, b2, b3, lmaddr + ng * 32);
            mma16(oacc[ng * 2], a0, a1, a2, a3, b0, b1);
            mma16(oacc[ng * 2 + 1], a0, a1, a2, a3, b2, b3);
        }
    }

    float slo = psum[rowA], shi = psum[rowA + 8];
#pragma unroll
    for (int ww = 1; ww < 8; ww++) {
        slo += psum[ww * 64 + rowA];
        shi += psum[ww * 64 + rowA + 8];
    }
    float rlo = 1.0f / slo, rhi = 1.0f / shi;
#pragma unroll
    for (int nt = 0; nt < 4; nt++) {
        int d = sh * 32 + nt * 8 + c0 * 2;
        __half* olo = outp + (size_t)grp * outGroupStride
                    + (size_t)(i0 + rowA) * outPosStride + h * 64 + d;
        __half* ohi = outp + (size_t)grp * outGroupStride
                    + (size_t)(i0 + rowA + 8) * outPosStride + h * 64 + d;
        __half2 v0 = __floats2half2_rn(oacc[nt][0] * rlo, oacc[nt][1] * rlo);
        __half2 v1 = __floats2half2_rn(oacc[nt][2] * rhi, oacc[nt][3] * rhi);
        *(uint32_t*)olo = *(uint32_t*)&v0;
        *(uint32_t*)ohi = *(uint32_t*)&v1;
    }
}

#define ATTN_SMEM(S) (S * 144 * 2 + 64 * 144 + S * 4 + 4096)

// ------------------------- residual + LayerNorm (fp16 residual input; optional fp16 second output) ----
__global__ __launch_bounds__(256)
void ln_kernel(const float* __restrict__ x, const __half* __restrict__ r,
               const float* __restrict__ g, const float* __restrict__ b,
               float* __restrict__ out, __half* __restrict__ cvtout) {
    __shared__ float rs[8], rq[8], sh[2];
    int row = blockIdx.x, tid = threadIdx.x;
    size_t b0 = (size_t)row * DD;
    float v[3]; float s = 0.0f, q = 0.0f;
#pragma unroll
    for (int u = 0; u < 3; u++) {
        int c = tid + u * 256;
        float t = x[b0 + c] + __half2float(r[b0 + c]);
        v[u] = t; s += t; q += t * t;
    }
#pragma unroll
    for (int o = 16; o > 0; o >>= 1) {
        s += __shfl_down_sync(0xffffffffu, s, o);
        q += __shfl_down_sync(0xffffffffu, q, o);
    }
    int wid = tid >> 5, lane = tid & 31;
    if (lane == 0) { rs[wid] = s; rq[wid] = q; }
    __syncthreads();
    if (tid == 0) {
        float S = 0.0f, Q = 0.0f;
#pragma unroll
        for (int w = 0; w < 8; w++) { S += rs[w]; Q += rq[w]; }
        float mu = S * (1.0f / 768.0f);
        sh[0] = mu;
        sh[1] = rsqrtf(Q * (1.0f / 768.0f) - mu * mu + 1e-5f);
    }
    __syncthreads();
    float mu = sh[0], inv = sh[1];
#pragma unroll
    for (int u = 0; u < 3; u++) {
        int c = tid + u * 256;
        float o = (v[u] - mu) * inv * g[c] + b[c];
        out[b0 + c] = o;
        if (cvtout) cvtout[b0 + c] = __float2half_rn(o);
    }
}

// ------------------------- launch -------------------------
extern "C" void kernel_launch(void* const* d_in, const int* in_sizes, int n_in,
                              void* d_out, int out_size) {
    const float* x     = (const float*)d_in[0];
    const float* w_row = (const float*)d_in[1];
    const float* b_row = (const float*)d_in[2];
    const float* w_col = (const float*)d_in[3];
    const float* b_col = (const float*)d_in[4];
    const float* g1    = (const float*)d_in[5];
    const float* be1   = (const float*)d_in[6];
    const float* g2    = (const float*)d_in[7];
    const float* be2   = (const float*)d_in[8];
    const void*  mask  = d_in[9];
    float* out = (float*)d_out;

    float *neg;
    __half *qkvh, *tmph, *acvh, *wcvh;
    cudaGetSymbolAddress((void**)&qkvh, g_qkvh);
    cudaGetSymbolAddress((void**)&tmph, g_tmph);
    cudaGetSymbolAddress((void**)&acvh, g_acvh);
    cudaGetSymbolAddress((void**)&wcvh, g_wcvh);
    cudaGetSymbolAddress((void**)&neg, g_neg);

    cudaFuncSetAttribute(attn_tc_kernel<256>, cudaFuncAttributeMaxDynamicSharedMemorySize, ATTN_SMEM(256));
    cudaFuncSetAttribute(attn_tc_kernel<128>, cudaFuncAttributeMaxDynamicSharedMemorySize, ATTN_SMEM(128));
    cudaFuncSetAttribute(gemm_mma_kernel, cudaFuncAttributeMaxDynamicSharedMemorySize, GEMM_SMEM);

    neg_kernel<<<1, 256>>>(mask);

    dim3 ggrid(D3 / GN, NROWS / GM);   // (18, 256)
    const int ACV_BLKS = (int)(((size_t)NROWS * DD) / 2048);   // 12288
    const int WCV_BLKS = (int)(((size_t)D3 * DD) / 2048);      // 864

    // ---- row attention block ----
    cvt_h_kernel<<<ACV_BLKS, 256>>>(x, acvh);
    cvt_h_kernel<<<WCV_BLKS, 256>>>(w_row, wcvh);
    gemm_mma_kernel<<<ggrid, 256, GEMM_SMEM>>>(acvh, wcvh, b_row, qkvh);
    {
        dim3 agrid(LL / 64, 12, EE);
        attn_tc_kernel<256><<<agrid, 256, ATTN_SMEM(256)>>>(
            qkvh, (long)LL * D3, (long)D3,
            neg, (long)LL, 1L,
            tmph, (long)LL * DD, (long)DD);
    }
    ln_kernel<<<NROWS, 256>>>(x, tmph, g1, be1, out, acvh);   // dual-write: fp32 + fp16

    // ---- column attention block ----
    cvt_h_kernel<<<WCV_BLKS, 256>>>(w_col, wcvh);
    gemm_mma_kernel<<<ggrid, 256, GEMM_SMEM>>>(acvh, wcvh, b_col, qkvh);
    {
        dim3 agrid(EE / 64, 12, LL);
        attn_tc_kernel<128><<<agrid, 256, ATTN_SMEM(128)>>>(
            qkvh, (long)D3, (long)LL * D3,
            neg, 1L, (long)LL,
            tmph, (long)DD, (long)LL * DD);
    }
    ln_kernel<<<NROWS, 256>>>(out, tmph, g2, be2, out, (__half*)0);
}